// round 16
// baseline (speedup 1.0000x reference)
#include <cuda_runtime.h>
#include <cuda_bf16.h>
#include <math.h>

#define NROWS 65536
#define EDIM  1024
#define KST   4
#define DDIM  5
#define NBLK  304
#define WPB   8
#define NWARPS (NBLK * WPB)

typedef unsigned long long ull;

// 16-byte vector of two packed f32x2 operands (loads emit LDG.128/LDS.128,
// halves feed fma.rn.f32x2 directly with no MOV64 packing)
struct __align__(16) ull2v { ull x, y; };

__device__ float g_row_norm[NROWS];

__constant__ int c_lo[5] = {0, 0, 0, 1, 2};   // valid step index range per dim
__constant__ int c_hi[5] = {7, 7, 7, 6, 6};   // steps = idx - 4  ->  [-4..3]

// ---- packed f32x2 helpers (ptxas never emits FFMA2 from C++) ----
__device__ __forceinline__ ull pk2(float lo, float hi) {
    ull r; asm("mov.b64 %0, {%1, %2};" : "=l"(r) : "f"(lo), "f"(hi)); return r;
}
__device__ __forceinline__ void upk2(ull v, float& a, float& b) {
    asm("mov.b64 {%0, %1}, %2;" : "=f"(a), "=f"(b) : "l"(v));
}
__device__ __forceinline__ ull ffma2_(ull a, ull b, ull c) {
    ull d; asm("fma.rn.f32x2 %0, %1, %2, %3;" : "=l"(d) : "l"(a), "l"(b), "l"(c));
    return d;
}
__device__ __forceinline__ float hsum2(ull v) {
    float x, y; upk2(v, x, y); return x + y;
}

// ---- main fused kernel: 2 rows per warp, persistent blocks ----
__global__ __launch_bounds__(256, 2) void qmain(
    const float* __restrict__ h_in,
    const float* __restrict__ Wp,     // (K, D, E)
    const float* __restrict__ bp,     // (K, D)
    const float* __restrict__ Wi,     // (K, E, D)
    const float* __restrict__ bi,     // (K, E)
    const float* __restrict__ temp,   // (1,)
    const float* __restrict__ u,      // (K, N, D, C)
    const float* __restrict__ p,      // (N,)
    float* __restrict__ out_q,        // (N, E)
    float* __restrict__ out_code)     // (N, K*D)
{
    extern __shared__ float smem[];
    float* sWi = smem;                         // (K*D)*E, d-major transposed Wi
    float* sG  = smem + KST * DDIM * EDIM;     // WPB * 320 gumbels (2 rows/warp)

    const int t    = threadIdx.x;
    const int lane = t & 31;
    const int warp = t >> 5;

    // ---- one-time per block: transpose Wi (K,E,D) -> sWi[(i*D+d)*E + e] ----
    for (int idx = t; idx < KST * EDIM * DDIM; idx += 256) {
        int i   = idx / (EDIM * DDIM);
        int rem = idx - i * (EDIM * DDIM);
        int e   = rem / DDIM;
        int d   = rem - e * DDIM;
        sWi[(i * DDIM + d) * EDIM + e] = Wi[idx];
    }
    __syncthreads();

    float te = temp[0];
    te = fmaxf(te * te, 1e-8f);
    const float inv_t2 = 1.0f / (te * te);
    const ull NEG1 = pk2(-1.0f, -1.0f);

    // ---- per-lane quantizer constants (lanes 0..4 -> rowA dims, 8..12 -> rowB) ----
    const bool qlaneA = (lane < 5);
    const bool qlaneB = (lane >= 8 && lane < 13);
    const int  qd     = qlaneA ? lane : (qlaneB ? (lane - 8) : 0);
    float k_shift = 0.f, k_half_l = 1.f, k_off = 0.f, k_halfw = 1.f;
    if (qlaneA || qlaneB) {
        double lev = (qd < 3) ? 8.0 : ((qd == 3) ? 6.0 : 5.0);
        double half_l = (lev - 1.0) * (1.0 - 1e-3) / 2.0;
        double off_b  = (((int)lev) & 1) ? 0.0 : 0.5;
        k_half_l = (float)half_l;
        k_off    = (float)off_b;
        k_shift  = (float)tan(off_b / half_l);
        k_halfw  = (float)((int)lev / 2);
    }
    const int q_lo = c_lo[qd], q_hi = c_hi[qd];

    float* sGw = sG + warp * 320;
    const int gwarp = blockIdx.x * WPB + warp;

    for (int rowA = 2 * gwarp; rowA < NROWS; rowA += 2 * NWARPS) {
        const int rowB = rowA + 1;

        // ---- precompute gumbels for both rows (coalesced) ----
        #pragma unroll
        for (int kk = 0; kk < 10; kk++) {
            int idx = kk * 32 + lane;                   // 0..319
            int rsel = idx / 160;                       // 0=A, 1=B
            int j    = idx - rsel * 160;
            int i    = j / 40;
            int r40  = j - i * 40;
            float uu = __ldcs(u + ((size_t)i * NROWS + (rowA + rsel)) * 40 + r40);
            sGw[idx] = -logf(-logf(uu + 1e-20f) + 1e-20f);
        }
        __syncwarp();

        // ---- load residuals directly as packed f32x2 pairs ----
        const ull2v* hA = (const ull2v*)(h_in + (size_t)rowA * EDIM);
        const ull2v* hB = (const ull2v*)(h_in + (size_t)rowB * EDIM);
        ull rA[16], rB[16];
        ull hhAp = 0ull, hhBp = 0ull;
        #pragma unroll
        for (int jj = 0; jj < 8; jj++) {
            ull2v va = hA[jj * 32 + lane];
            ull2v vb = hB[jj * 32 + lane];
            rA[2*jj] = va.x;  rA[2*jj+1] = va.y;
            rB[2*jj] = vb.x;  rB[2*jj+1] = vb.y;
            hhAp = ffma2_(rA[2*jj], rA[2*jj], hhAp);
            hhAp = ffma2_(rA[2*jj+1], rA[2*jj+1], hhAp);
            hhBp = ffma2_(rB[2*jj], rB[2*jj], hhBp);
            hhBp = ffma2_(rB[2*jj+1], rB[2*jj+1], hhBp);
        }
        float hhA = hsum2(hhAp), hhB = hsum2(hhBp);

        const float prA = __ldg(p + rowA);
        const float prB = __ldg(p + rowB);
        float ssqA = 0.f, ssqB = 0.f;
        bool  selA = false, selB = false;

        #pragma unroll
        for (int i = 0; i < KST; i++) {
            // ---- projection: shared weight loads feed both rows ----
            float pdA[5], pdB[5];
            const float* wpb_ = Wp + (size_t)i * DDIM * EDIM;
            #pragma unroll
            for (int d = 0; d < 5; d++) {
                const ull2v* wr = (const ull2v*)(wpb_ + d * EDIM);
                ull aA = 0ull, aB = 0ull;
                #pragma unroll
                for (int jj = 0; jj < 8; jj++) {
                    ull2v w = wr[jj * 32 + lane];
                    aA = ffma2_(w.x, rA[2*jj], aA);
                    aA = ffma2_(w.y, rA[2*jj+1], aA);
                    aB = ffma2_(w.x, rB[2*jj], aB);
                    aB = ffma2_(w.y, rB[2*jj+1], aB);
                }
                pdA[d] = hsum2(aA);
                pdB[d] = hsum2(aB);
            }
            #pragma unroll
            for (int d = 0; d < 5; d++) {
                #pragma unroll
                for (int off = 16; off; off >>= 1) {
                    pdA[d] += __shfl_xor_sync(0xffffffffu, pdA[d], off);
                    pdB[d] += __shfl_xor_sync(0xffffffffu, pdB[d], off);
                }
            }

            // ---- quantize: lanes 0..4 do rowA, lanes 8..12 do rowB ----
            float zq = 0.f;
            if (qlaneA || qlaneB) {
                float h = qlaneA ?
                    ((qd==0)?pdA[0]:(qd==1)?pdA[1]:(qd==2)?pdA[2]:(qd==3)?pdA[3]:pdA[4]) :
                    ((qd==0)?pdB[0]:(qd==1)?pdB[1]:(qd==2)?pdB[2]:(qd==3)?pdB[3]:pdB[4]);
                h += __ldg(bp + i * DDIM + qd);
                float z = tanhf(h + k_shift) * k_half_l - k_off;

                const float* gp = sGw + (qlaneB ? 160 : 0) + i * 40 + qd * 8;
                float best = -INFINITY;
                int bc = q_lo;
                #pragma unroll
                for (int c = 0; c < 8; c++) {
                    if (c >= q_lo && c <= q_hi) {
                        float df  = z - (float)(c - 4);
                        float val = -(df * df) * inv_t2 + gp[c];
                        if (val > best) { best = val; bc = c; }  // first-max tie-break
                    }
                }
                zq = (float)(bc - 4) / k_halfw;
                size_t row = qlaneA ? (size_t)rowA : (size_t)rowB;
                __stcs(out_code + row * (KST * DDIM) + i * DDIM + qd, zq);
            }
            float za0 = __shfl_sync(0xffffffffu, zq, 0);
            float za1 = __shfl_sync(0xffffffffu, zq, 1);
            float za2 = __shfl_sync(0xffffffffu, zq, 2);
            float za3 = __shfl_sync(0xffffffffu, zq, 3);
            float za4 = __shfl_sync(0xffffffffu, zq, 4);
            float zb0 = __shfl_sync(0xffffffffu, zq, 8);
            float zb1 = __shfl_sync(0xffffffffu, zq, 9);
            float zb2 = __shfl_sync(0xffffffffu, zq, 10);
            float zb3 = __shfl_sync(0xffffffffu, zq, 11);
            float zb4 = __shfl_sync(0xffffffffu, zq, 12);
            const ull zA0 = pk2(za0, za0), zA1 = pk2(za1, za1), zA2 = pk2(za2, za2);
            const ull zA3 = pk2(za3, za3), zA4 = pk2(za4, za4);
            const ull zB0 = pk2(zb0, zb0), zB1 = pk2(zb1, zb1), zB2 = pk2(zb2, zb2);
            const ull zB3 = pk2(zb3, zb3), zB4 = pk2(zb4, zb4);

            // ---- inverse projection from smem, weights shared by both rows ----
            const ull2v* s0 = (const ull2v*)(sWi + (i * DDIM + 0) * EDIM);
            const ull2v* s1 = (const ull2v*)(sWi + (i * DDIM + 1) * EDIM);
            const ull2v* s2 = (const ull2v*)(sWi + (i * DDIM + 2) * EDIM);
            const ull2v* s3 = (const ull2v*)(sWi + (i * DDIM + 3) * EDIM);
            const ull2v* s4 = (const ull2v*)(sWi + (i * DDIM + 4) * EDIM);
            const ull2v* bv2 = (const ull2v*)(bi + (size_t)i * EDIM);
            #pragma unroll
            for (int jj = 0; jj < 8; jj++) {
                int e4 = jj * 32 + lane;
                ull2v w0 = s0[e4], w1 = s1[e4], w2 = s2[e4], w3 = s3[e4], w4 = s4[e4];
                ull2v bb = bv2[e4];

                ull tl = bb.x;
                tl = ffma2_(w0.x, zA0, tl); tl = ffma2_(w1.x, zA1, tl);
                tl = ffma2_(w2.x, zA2, tl); tl = ffma2_(w3.x, zA3, tl);
                tl = ffma2_(w4.x, zA4, tl);
                rA[2*jj] = ffma2_(tl, NEG1, rA[2*jj]);
                ull th = bb.y;
                th = ffma2_(w0.y, zA0, th); th = ffma2_(w1.y, zA1, th);
                th = ffma2_(w2.y, zA2, th); th = ffma2_(w3.y, zA3, th);
                th = ffma2_(w4.y, zA4, th);
                rA[2*jj+1] = ffma2_(th, NEG1, rA[2*jj+1]);

                ull ul = bb.x;
                ul = ffma2_(w0.x, zB0, ul); ul = ffma2_(w1.x, zB1, ul);
                ul = ffma2_(w2.x, zB2, ul); ul = ffma2_(w3.x, zB3, ul);
                ul = ffma2_(w4.x, zB4, ul);
                rB[2*jj] = ffma2_(ul, NEG1, rB[2*jj]);
                ull uh = bb.y;
                uh = ffma2_(w0.y, zB0, uh); uh = ffma2_(w1.y, zB1, uh);
                uh = ffma2_(w2.y, zB2, uh); uh = ffma2_(w3.y, zB3, uh);
                uh = ffma2_(w4.y, zB4, uh);
                rB[2*jj+1] = ffma2_(uh, NEG1, rB[2*jj+1]);
            }

            // ---- loss selection: h_in - q_mix == residual after selected stage ----
            const float tlo = (float)i * 0.25f, thi = (float)(i + 1) * 0.25f;
            if ((tlo < prA) && (prA <= thi)) {
                ull sp = 0ull;
                #pragma unroll
                for (int k = 0; k < 16; k++) sp = ffma2_(rA[k], rA[k], sp);
                ssqA = hsum2(sp); selA = true;
            }
            if ((tlo < prB) && (prB <= thi)) {
                ull sp = 0ull;
                #pragma unroll
                for (int k = 0; k < 16; k++) sp = ffma2_(rB[k], rB[k], sp);
                ssqB = hsum2(sp); selB = true;
            }
        }

        // ---- q = h0 - r_final (h reread hits L1/L2) ----
        ull2v* qA = (ull2v*)(out_q + (size_t)rowA * EDIM);
        ull2v* qB = (ull2v*)(out_q + (size_t)rowB * EDIM);
        #pragma unroll
        for (int jj = 0; jj < 8; jj++) {
            ull2v ha = hA[jj * 32 + lane];
            ull2v hb = hB[jj * 32 + lane];
            ull2v qa, qb;
            qa.x = ffma2_(rA[2*jj],   NEG1, ha.x);
            qa.y = ffma2_(rA[2*jj+1], NEG1, ha.y);
            qb.x = ffma2_(rB[2*jj],   NEG1, hb.x);
            qb.y = ffma2_(rB[2*jj+1], NEG1, hb.y);
            __stcs((uint4*)(qA + jj * 32 + lane), *(const uint4*)&qa);
            __stcs((uint4*)(qB + jj * 32 + lane), *(const uint4*)&qb);
        }

        // ---- per-row norms ----
        float sa = selA ? ssqA : hhA;
        float sb = selB ? ssqB : hhB;
        #pragma unroll
        for (int off = 16; off; off >>= 1) {
            sa += __shfl_xor_sync(0xffffffffu, sa, off);
            sb += __shfl_xor_sync(0xffffffffu, sb, off);
        }
        if (lane == 0) {
            g_row_norm[rowA] = sqrtf(sa);
            g_row_norm[rowB] = sqrtf(sb);
        }
    }
}

// ---- deterministic mean of per-row norms (vectorized) ----
__global__ __launch_bounds__(1024) void qfinal(float* __restrict__ out_loss) {
    __shared__ float sh[1024];
    const float4* v = (const float4*)g_row_norm;
    float s = 0.f;
    for (int idx = threadIdx.x; idx < NROWS / 4; idx += 1024) {
        float4 a = v[idx];
        s += (a.x + a.y) + (a.z + a.w);
    }
    sh[threadIdx.x] = s;
    __syncthreads();
    for (int stride = 512; stride; stride >>= 1) {
        if (threadIdx.x < (unsigned)stride) sh[threadIdx.x] += sh[threadIdx.x + stride];
        __syncthreads();
    }
    if (threadIdx.x == 0) out_loss[0] = sh[0] / (float)NROWS;
}

extern "C" void kernel_launch(void* const* d_in, const int* in_sizes, int n_in,
                              void* d_out, int out_size) {
    const float* h_in = (const float*)d_in[0];
    const float* Wp   = (const float*)d_in[1];
    const float* bp   = (const float*)d_in[2];
    const float* Wi   = (const float*)d_in[3];
    const float* bi   = (const float*)d_in[4];
    const float* temp = (const float*)d_in[5];
    const float* u    = (const float*)d_in[6];
    const float* p    = (const float*)d_in[7];

    float* out      = (float*)d_out;
    float* out_q    = out;                                   // (N, E)
    float* out_code = out + (size_t)NROWS * EDIM;            // (N, K*D)
    float* out_loss = out_code + (size_t)NROWS * KST * DDIM; // scalar

    const int smem_bytes = (KST * DDIM * EDIM + WPB * 320) * (int)sizeof(float); // 92160
    cudaFuncSetAttribute(qmain, cudaFuncAttributeMaxDynamicSharedMemorySize, smem_bytes);

    qmain<<<NBLK, 256, smem_bytes>>>(h_in, Wp, bp, Wi, bi, temp, u, p, out_q, out_code);
    qfinal<<<1, 1024>>>(out_loss);
}